// round 17
// baseline (speedup 1.0000x reference)
#include <cuda_runtime.h>
#include <cuda_bf16.h>

// Problem constants
#define T_DIM 1024
#define B_DIM 128
#define C_DIM 256
#define L_DIM 64
#define S_DIM 129           // 2*L+1
#define BC    (B_DIM * C_DIM)
#define NEGV  (-1e30f)
#define LOG2E 1.4426950408889634f
#define LN2   0.6931471805599453f

#define NSLOT 12            // smem row ring slots
#define N_ENT_BLOCKS 1024
#define THREADS 256

// Deterministic two-stage reduction scratch (fully overwritten every call)
__device__ float g_ent_part[N_ENT_BLOCKS];
__device__ float g_ctc_part[B_DIM];

#define CP_ASYNC_16(dst_smem_u32, src_gptr) \
    asm volatile("cp.async.cg.shared.global [%0], [%1], 16;" :: "r"(dst_smem_u32), "l"(src_gptr))
#define CP_ASYNC_COMMIT() asm volatile("cp.async.commit_group;")
#define CP_ASYNC_WAIT(n)  asm volatile("cp.async.wait_group %0;" :: "n"(n))

__device__ __forceinline__ float ex2f(float x) {
    float r; asm("ex2.approx.f32 %0, %1;" : "=f"(r) : "f"(x)); return r;
}
__device__ __forceinline__ float lg2f(float x) {
    float r; asm("lg2.approx.f32 %0, %1;" : "=f"(r) : "f"(x)); return r;
}
// log2-domain logsumexp3 (NEGV-safe: lse3(x,NEGV,NEGV) == x)
__device__ __forceinline__ float lse3(float x, float y, float z) {
    float m = fmaxf(x, fmaxf(y, z));
    return m + lg2f(ex2f(x - m) + ex2f(y - m) + ex2f(z - m));
}

__global__ void __launch_bounds__(THREADS)
fused_ctc_entropy(const float* __restrict__ lp,
                  const int* __restrict__ targets,
                  const int* __restrict__ in_len,
                  const int* __restrict__ tgt_len)
{
    const int tid = threadIdx.x;

    __shared__ float rows[NSLOT][C_DIM];   // staged RAW log_prob rows (12 KB)
    __shared__ float buf[2][S_DIM + 4];    // [pad4 | states 0..128], double buffered
    __shared__ float cap[2];
    __shared__ float red[THREADS / 32];

    if (blockIdx.x < B_DIM) {
        // ===== CTC DP block: 2 steps per barrier, warp-specialized =====
        //   warps 0-3 (tid<128): DP compute, thread k -> state k+1 (+state 0 on k=0)
        //   warps 4-5 (tid 128-191): cp.async loaders (2 rows per group)
        //   warps 6-7: exit
        if (tid >= 192) return;

        const int b = blockIdx.x;
        const int Tlen = in_len[b];          // in [T/2, T]
        const float* rowbase = lp + b * C_DIM;

        if (tid >= 128) {
            // ---------------- loader warps ----------------
            const int lt = tid - 128;        // 0..63, one float4 per thread
            // Prime 4 groups: rows (1,2),(3,4),(5,6),(7,8)
            #pragma unroll
            for (int g = 0; g < 4; ++g) {
                int r0 = 1 + 2 * g, r1 = 2 + 2 * g;
                const float4* s0 = (const float4*)(rowbase + r0 * BC);
                const float4* s1 = (const float4*)(rowbase + r1 * BC);
                unsigned d0 = (unsigned)__cvta_generic_to_shared((float4*)rows[r0 % NSLOT] + lt);
                unsigned d1 = (unsigned)__cvta_generic_to_shared((float4*)rows[r1 % NSLOT] + lt);
                CP_ASYNC_16(d0, s0 + lt);
                CP_ASYNC_16(d1, s1 + lt);
                CP_ASYNC_COMMIT();
            }
            CP_ASYNC_WAIT(2);                // rows 1..4 landed
            __syncthreads();                 // pre-loop sync (with compute warps)

            for (int t = 1; t + 1 < Tlen; t += 2) {
                CP_ASYNC_WAIT(2);            // rows <= t+3 landed
                __syncthreads();             // per-iteration barrier
                int ra = t + 8; if (ra > T_DIM - 1) ra = T_DIM - 1;
                int rb = t + 9; if (rb > T_DIM - 1) rb = T_DIM - 1;
                const float4* sa = (const float4*)(rowbase + ra * BC);
                const float4* sb = (const float4*)(rowbase + rb * BC);
                unsigned da = (unsigned)__cvta_generic_to_shared(
                    (float4*)rows[(t + 8) % NSLOT] + lt);
                unsigned db = (unsigned)__cvta_generic_to_shared(
                    (float4*)rows[(t + 9) % NSLOT] + lt);
                CP_ASYNC_16(da, sa + lt);
                CP_ASYNC_16(db, sb + lt);
                CP_ASYNC_COMMIT();
            }
            CP_ASYNC_WAIT(0);                // drain; exit (later barriers count live warps)
            return;
        }

        // ---------------- DP compute warps (tid < 128) ----------------
        const int s = tid + 1;               // this thread's state (1..128)

        if (tid < 4) { buf[0][tid] = NEGV; buf[1][tid] = NEGV; }  // pad4

        const int* tg = targets + b * L_DIM;
        // labels + skip flags for states s, s-1, s-2 (blank states: label 0, no skip)
        int  lab_s = 0, lab_m1 = 0, lab_m2 = 0;
        bool al_s = false, al_m1 = false, al_m2 = false;
        if (s & 1) {                         // s odd
            int j = s >> 1;
            lab_s = tg[j];
            al_s  = (j == 0) || (lab_s != tg[j - 1]);
            // s-1, s-2: s-1 even (blank), s-2 odd
            if (s >= 3) {
                int j2 = (s - 2) >> 1;
                lab_m2 = tg[j2];
                al_m2  = (j2 == 0) || (lab_m2 != tg[j2 - 1]);
            }
        } else {                             // s even (blank); s-1 odd
            int j1 = (s - 1) >> 1;
            lab_m1 = tg[j1];
            al_m1  = (j1 == 0) || (lab_m1 != tg[j1 - 1]);
        }
        const int tl = tgt_len[b];

        // t = 0 init (log2 units); thread 0 also owns state 0
        float a  = NEGV;
        float a0 = 0.0f;
        if (tid == 0) {
            a  = rowbase[lab_s] * LOG2E;     // state 1
            a0 = rowbase[0]     * LOG2E;     // state 0 (blank)
        }

        __syncthreads();                     // pads + rows 1..4 visible

        // off-chain prefetch for iteration t=1: rows 1 (b-layer) and 2 (a-layer)
        float pS  = rows[1][lab_s]  * LOG2E;  // row t,   label(s)
        float pM1 = rows[1][lab_m1] * LOG2E;  // row t,   label(s-1)
        float pM2 = rows[1][lab_m2] * LOG2E;  // row t,   label(s-2)
        float qS  = rows[2][lab_s]  * LOG2E;  // row t+1, label(s)
        float pB  = rows[1][0] * LOG2E;       // blank, row t   (state 0)
        float qB  = rows[2][0] * LOG2E;       // blank, row t+1 (state 0)

        int p = 0;
        int t = 1;
        for (; t + 1 < Tlen; t += 2) {
            buf[p][4 + s] = a;
            if (tid == 0) buf[p][4] = a0;    // state 0
            __syncthreads();                 // loaders guarantee rows <= t+3 landed

            float A1 = buf[p][3 + s];        // alpha_{s-1}
            float A2 = buf[p][2 + s];        // alpha_{s-2}
            float A3 = buf[p][1 + s];        // alpha_{s-3}
            float A4 = buf[p][0 + s];        // alpha_{s-4}

            // b-layer (time t) for states s, s-1, s-2 (NEGV pads make edges exact)
            float bS  = lse3(a,  A1, al_s  ? A2 : NEGV) + pS;
            float bM1 = lse3(A1, A2, al_m1 ? A3 : NEGV) + pM1;
            float bM2 = lse3(A2, A3, al_m2 ? A4 : NEGV) + pM2;

            // a-layer (time t+1)
            a = lse3(bS, bM1, al_s ? bM2 : NEGV) + qS;
            if (tid == 0) a0 += pB + qB;     // state 0: self-loop only

            // off-chain prefetch for next iteration (rows t+2, t+3 resident)
            const float* r2 = rows[(t + 2) % NSLOT];
            const float* r3 = rows[(t + 3) % NSLOT];
            pS  = r2[lab_s]  * LOG2E;
            pM1 = r2[lab_m1] * LOG2E;
            pM2 = r2[lab_m2] * LOG2E;
            qS  = r3[lab_s]  * LOG2E;
            if (tid == 0) { pB = r2[0] * LOG2E; qB = r3[0] * LOG2E; }
            p ^= 1;
        }

        if (t < Tlen) {
            // tail single step t = Tlen-1 (loaders exited; row t landed at last loop barrier)
            buf[p][4 + s] = a;
            if (tid == 0) buf[p][4] = a0;
            __syncthreads();
            const float* rt = rows[t % NSLOT];
            float A1 = buf[p][3 + s];
            float A2 = buf[p][2 + s];
            a = lse3(a, A1, al_s ? A2 : NEGV) + rt[lab_s] * LOG2E;
            if (tid == 0) a0 += rt[0] * LOG2E;
            p ^= 1;
        }

        // a holds alpha (log2) at t = Tlen-1 for state tid+1; capture end states
        if (tid == 2 * tl - 1) cap[0] = a;   // state 2*tl
        if (tid == 2 * tl - 2) cap[1] = a;   // state 2*tl-1
        __syncthreads();

        if (tid == 0) {
            float a1 = cap[0], ae = cap[1];
            float m  = fmaxf(a1, ae);
            float ll2v = m + lg2f(ex2f(a1 - m) + ex2f(ae - m));
            float nll = -(ll2v * LN2);
            g_ctc_part[b] = (nll > 1e29f) ? 0.0f : nll;   // zero_infinity
        }
    } else {
        // ================= Entropy block: sum exp(lp)*lp =================
        const int eb = blockIdx.x - B_DIM;
        const float4* v = (const float4*)lp;
        const int n4 = (T_DIM * B_DIM * C_DIM) / 4;

        float acc = 0.0f;
        for (int i = eb * THREADS + tid; i < n4; i += N_ENT_BLOCKS * THREADS) {
            float4 x = v[i];
            acc += __expf(x.x) * x.x;
            acc += __expf(x.y) * x.y;
            acc += __expf(x.z) * x.z;
            acc += __expf(x.w) * x.w;
        }

        #pragma unroll
        for (int o = 16; o > 0; o >>= 1)
            acc += __shfl_down_sync(0xFFFFFFFFu, acc, o);
        if ((tid & 31) == 0) red[tid >> 5] = acc;
        __syncthreads();
        if (tid < THREADS / 32) {
            float r = red[tid];
            #pragma unroll
            for (int o = (THREADS / 64); o > 0; o >>= 1)
                r += __shfl_down_sync(0xFFFFFFFFu, r, o);
            if (tid == 0) g_ent_part[eb] = r;
        }
    }
}

__global__ void __launch_bounds__(256)
finalize_kernel(float* __restrict__ out)
{
    const int tid = threadIdx.x;
    float acc = 0.0f;
    for (int i = tid; i < N_ENT_BLOCKS; i += 256) acc += g_ent_part[i];

    float c = (tid < B_DIM) ? g_ctc_part[tid] : 0.0f;

    __shared__ float red[8], redc[8];
    #pragma unroll
    for (int o = 16; o > 0; o >>= 1) {
        acc += __shfl_down_sync(0xFFFFFFFFu, acc, o);
        c   += __shfl_down_sync(0xFFFFFFFFu, c, o);
    }
    if ((tid & 31) == 0) { red[tid >> 5] = acc; redc[tid >> 5] = c; }
    __syncthreads();
    if (tid == 0) {
        float es = 0.0f, cs = 0.0f;
        #pragma unroll
        for (int i = 0; i < 8; ++i) { es += red[i]; cs += redc[i]; }
        float smooth   = es / (float)(T_DIM * B_DIM);
        float ctc_mean = cs / (float)B_DIM;
        out[0] = 0.9f * ctc_mean + 0.1f * smooth;
    }
}

extern "C" void kernel_launch(void* const* d_in, const int* in_sizes, int n_in,
                              void* d_out, int out_size)
{
    const float* lp      = (const float*)d_in[0];
    const int*   targets = (const int*)d_in[1];
    const int*   in_len  = (const int*)d_in[2];
    const int*   tgt_len = (const int*)d_in[3];
    float*       out     = (float*)d_out;

    fused_ctc_entropy<<<B_DIM + N_ENT_BLOCKS, THREADS>>>(lp, targets, in_len, tgt_len);
    finalize_kernel<<<1, 256>>>(out);
}